// round 11
// baseline (speedup 1.0000x reference)
#include <cuda_runtime.h>
#include <cuda_bf16.h>
#include <math.h>
#include <stdint.h>

// Problem constants
#define NG    4096
#define KPOS  4
#define H     256
#define MNEG  64
#define NROWS (NG * KPOS)       // 16384 embedding rows
#define KDIM  768               // (KPOS-1)*H
#define LDAH  1024              // halves per emb row-group in g_Ebf (KPOS*H)
#define NLOG  65

#define ZSPLIT 4
#define KS    (KDIM / ZSPLIT)   // 192 k per z-block

// Scratch (static device arrays; allocation-free rule)
__device__ __align__(16) __nv_bfloat16 g_Ebf[NROWS * H];   // full emb, bf16 (8 MB)
__device__ __align__(16) __nv_bfloat16 g_WTbf[H * KDIM];   // W^T, bf16, [n][k]
__device__ float g_pred4[ZSPLIT * NG * H];                 // split-K partials

// ---------------------------------------------------------------------------
// Kernel 0: convert. emb -> bf16 (16 floats/thread, 2 independent LDG.128
// pairs in flight); W -> bf16 transposed via 32x32 smem tile. Block 0 zeroes
// the output accumulator (graph-ordered before loss_kernel's atomics).
// ---------------------------------------------------------------------------
#define EMB_UNITS  (NROWS * H / 16)       // 262144 16-float units
#define EMB_BLOCKS (EMB_UNITS / 256)      // 1024
#define WT_TILES   ((KDIM / 32) * (H / 32))   // 192

__global__ __launch_bounds__(256) void convert_kernel(const float* __restrict__ emb,
                                                      const float* __restrict__ W,
                                                      float* __restrict__ out) {
    int b = blockIdx.x;
    if (b == 0 && threadIdx.x == 0) out[0] = 0.0f;   // reset accumulator
    if (b < EMB_BLOCKS) {
        size_t idx = (size_t)(b * 256 + threadIdx.x) * 16;
        const float4* src = (const float4*)(emb + idx);
        float4 v0 = src[0];
        float4 v1 = src[1];
        float4 v2 = src[2];
        float4 v3 = src[3];
        uint4 o0, o1;
        *(__nv_bfloat162*)&o0.x = __floats2bfloat162_rn(v0.x, v0.y);
        *(__nv_bfloat162*)&o0.y = __floats2bfloat162_rn(v0.z, v0.w);
        *(__nv_bfloat162*)&o0.z = __floats2bfloat162_rn(v1.x, v1.y);
        *(__nv_bfloat162*)&o0.w = __floats2bfloat162_rn(v1.z, v1.w);
        *(__nv_bfloat162*)&o1.x = __floats2bfloat162_rn(v2.x, v2.y);
        *(__nv_bfloat162*)&o1.y = __floats2bfloat162_rn(v2.z, v2.w);
        *(__nv_bfloat162*)&o1.z = __floats2bfloat162_rn(v3.x, v3.y);
        *(__nv_bfloat162*)&o1.w = __floats2bfloat162_rn(v3.z, v3.w);
        *(uint4*)&g_Ebf[idx] = o0;
        *(uint4*)&g_Ebf[idx + 8] = o1;
    } else {
        // W^T tile transpose: tile covers k0..k0+31, n0..n0+31
        __shared__ float tile[32][33];
        int b2 = b - EMB_BLOCKS;
        int n0 = (b2 & 7) * 32;
        int k0 = (b2 >> 3) * 32;
        int tx = threadIdx.x & 31;
        int ty = threadIdx.x >> 5;        // 0..7
#pragma unroll
        for (int i = 0; i < 4; i++) {
            int k = ty + 8 * i;
            tile[k][tx] = W[(size_t)(k0 + k) * H + n0 + tx];  // coalesced read
        }
        __syncthreads();
#pragma unroll
        for (int i = 0; i < 4; i++) {
            int n = ty + 8 * i;
            g_WTbf[(size_t)(n0 + n) * KDIM + k0 + tx] =
                __float2bfloat16_rn(tile[tx][n]);             // coalesced write
        }
    }
}

// ---------------------------------------------------------------------------
// Kernel A: predicts = hist_x @ W + b  via bf16 mma.m16n8k16, fp32 accum.
// BM=64 BN=64 BK=16, 128 threads = 4 warps (2x2), warp tile 32x32.
// Grid (4, 64, 4): z = split-K quarter (K=192 each) into g_pred4.
// ---------------------------------------------------------------------------
#define BKH 16                       // k halves per iteration
#define ITERS (KS / BKH)             // 12
#define STG 4
#define ROWH 24                      // padded halves per smem row (conflict-free)
#define A_ST_H (64 * ROWH)           // 1536 halves
#define STAGE_H (2 * A_ST_H)         // 3072 halves = 6144 B

__device__ __forceinline__ void cp16b(__nv_bfloat16* dst_smem, const __nv_bfloat16* src) {
    uint32_t d = (uint32_t)__cvta_generic_to_shared(dst_smem);
    asm volatile("cp.async.cg.shared.global [%0], [%1], 16;\n" :: "r"(d), "l"(src));
}

__global__ __launch_bounds__(128) void gemm_bf16(const float* __restrict__ bias) {
    __shared__ __align__(16) __nv_bfloat16 smem[STG * STAGE_H];

    const int tid  = threadIdx.x;
    const int warp = tid >> 5;
    const int lane = tid & 31;
    const int gid  = lane >> 2;          // mma groupID
    const int tq   = lane & 3;           // mma threadID-in-group
    const int wm0  = (warp >> 1) * 32;
    const int wn0  = (warp & 1) * 32;
    const int bm0  = blockIdx.y * 64;
    const int bn0  = blockIdx.x * 64;
    const int kz   = blockIdx.z * KS;

    const int crow = tid >> 1;           // 0..63
    const int koff = (tid & 1) * 8;      // halves

    const __nv_bfloat16* Asrc = g_Ebf  + (size_t)(bm0 + crow) * LDAH + kz + koff;
    const __nv_bfloat16* Bsrc = g_WTbf + (size_t)(bn0 + crow) * KDIM + kz + koff;

    float c[2][4][4];
#pragma unroll
    for (int i = 0; i < 2; i++)
#pragma unroll
        for (int j = 0; j < 4; j++)
#pragma unroll
            for (int q = 0; q < 4; q++) c[i][j][q] = 0.0f;

#pragma unroll
    for (int s = 0; s < STG - 1; s++) {
        __nv_bfloat16* st = smem + s * STAGE_H;
        cp16b(st + crow * ROWH + koff, Asrc + s * BKH);
        cp16b(st + A_ST_H + crow * ROWH + koff, Bsrc + s * BKH);
        asm volatile("cp.async.commit_group;\n" ::: "memory");
    }

#pragma unroll 4
    for (int it = 0; it < ITERS; it++) {
        asm volatile("cp.async.wait_group 2;\n" ::: "memory");
        __syncthreads();

        int nit = it + STG - 1;
        if (nit < ITERS) {
            __nv_bfloat16* st = smem + (nit % STG) * STAGE_H;
            cp16b(st + crow * ROWH + koff, Asrc + nit * BKH);
            cp16b(st + A_ST_H + crow * ROWH + koff, Bsrc + nit * BKH);
        }
        asm volatile("cp.async.commit_group;\n" ::: "memory");

        const __nv_bfloat16* As = smem + (it % STG) * STAGE_H;
        const __nv_bfloat16* Bs = As + A_ST_H;

        uint32_t a[2][4], b[4][2];
#pragma unroll
        for (int mf = 0; mf < 2; mf++) {
            int m = wm0 + mf * 16 + gid;
            a[mf][0] = *(const uint32_t*)&As[m * ROWH + 2 * tq];
            a[mf][1] = *(const uint32_t*)&As[(m + 8) * ROWH + 2 * tq];
            a[mf][2] = *(const uint32_t*)&As[m * ROWH + 2 * tq + 8];
            a[mf][3] = *(const uint32_t*)&As[(m + 8) * ROWH + 2 * tq + 8];
        }
#pragma unroll
        for (int nf = 0; nf < 4; nf++) {
            int n = wn0 + nf * 8 + gid;
            b[nf][0] = *(const uint32_t*)&Bs[n * ROWH + 2 * tq];
            b[nf][1] = *(const uint32_t*)&Bs[n * ROWH + 2 * tq + 8];
        }
#pragma unroll
        for (int mf = 0; mf < 2; mf++)
#pragma unroll
            for (int nf = 0; nf < 4; nf++) {
                asm volatile(
                    "mma.sync.aligned.m16n8k16.row.col.f32.bf16.bf16.f32 "
                    "{%0,%1,%2,%3}, {%4,%5,%6,%7}, {%8,%9}, {%0,%1,%2,%3};"
                    : "+f"(c[mf][nf][0]), "+f"(c[mf][nf][1]),
                      "+f"(c[mf][nf][2]), "+f"(c[mf][nf][3])
                    : "r"(a[mf][0]), "r"(a[mf][1]), "r"(a[mf][2]), "r"(a[mf][3]),
                      "r"(b[nf][0]), "r"(b[nf][1]));
            }
    }

    float* outb = g_pred4 + (size_t)blockIdx.z * NG * H;
#pragma unroll
    for (int mf = 0; mf < 2; mf++) {
        int m = bm0 + wm0 + mf * 16 + gid;
#pragma unroll
        for (int nf = 0; nf < 4; nf++) {
            int n = bn0 + wn0 + nf * 8 + 2 * tq;
            float bx = 0.0f, by = 0.0f;
            if (blockIdx.z == 0) {
                float2 bb = *(const float2*)(bias + n);
                bx = bb.x; by = bb.y;
            }
            *(float2*)&outb[(size_t)m * H + n] =
                make_float2(c[mf][nf][0] + bx, c[mf][nf][1] + by);
            *(float2*)&outb[(size_t)(m + 8) * H + n] =
                make_float2(c[mf][nf][2] + bx, c[mf][nf][3] + by);
        }
    }
}

// ---------------------------------------------------------------------------
// Kernel B: per-group logits + log-softmax term -> atomicAdd into out[0].
// Gather x4-unrolled: rows j, j+8, j+16, j+24 in flight per warp iteration.
// ---------------------------------------------------------------------------
__device__ __forceinline__ float dot_row(uint4 v, float4 pa, float4 pb) {
    float2 f0 = __bfloat1622float2(*(const __nv_bfloat162*)&v.x);
    float2 f1 = __bfloat1622float2(*(const __nv_bfloat162*)&v.y);
    float2 f2 = __bfloat1622float2(*(const __nv_bfloat162*)&v.z);
    float2 f3 = __bfloat1622float2(*(const __nv_bfloat162*)&v.w);
    return f0.x * pa.x + f0.y * pa.y + f1.x * pa.z + f1.y * pa.w
         + f2.x * pb.x + f2.y * pb.y + f3.x * pb.z + f3.y * pb.w;
}

__global__ __launch_bounds__(256) void loss_kernel(const int* __restrict__ perm,
                                                   float* __restrict__ out) {
    const int g    = blockIdx.x;
    const int tid  = threadIdx.x;
    const int warp = tid >> 5;
    const int lane = tid & 31;

    __shared__ float s_pred[H];
    __shared__ float s_logits[NLOG];
    __shared__ int   s_row[NLOG];

    {
        const float* pp = g_pred4 + (size_t)g * H + tid;
        s_pred[tid] = (pp[0] + pp[(size_t)NG * H])
                    + (pp[2 * (size_t)NG * H] + pp[3 * (size_t)NG * H]);
    }
    if (tid < MNEG) {
        int p = perm[(size_t)g * MNEG + tid];
        s_row[tid + 1] = p + ((p >= 4 * g) ? 4 : 0);
    }
    if (tid == MNEG) s_row[0] = 4 * g + 3;
    __syncthreads();

    // each lane owns 8 consecutive pred floats (halves 8*lane .. 8*lane+7)
    const float4* p4 = (const float4*)s_pred;
    const float4 pa = p4[2 * lane];
    const float4 pb = p4[2 * lane + 1];

    // x4 unrolled gather: rows j, j+8, j+16, j+24 in flight together
    for (int j = warp; j < NLOG; j += 32) {
        bool h1 = (j + 8) < NLOG;
        bool h2 = (j + 16) < NLOG;
        bool h3 = (j + 24) < NLOG;
        uint4 v0 = ((const uint4*)(g_Ebf + (size_t)s_row[j] * H))[lane];
        uint4 v1 = h1 ? ((const uint4*)(g_Ebf + (size_t)s_row[j + 8] * H))[lane]
                      : make_uint4(0, 0, 0, 0);
        uint4 v2 = h2 ? ((const uint4*)(g_Ebf + (size_t)s_row[j + 16] * H))[lane]
                      : make_uint4(0, 0, 0, 0);
        uint4 v3 = h3 ? ((const uint4*)(g_Ebf + (size_t)s_row[j + 24] * H))[lane]
                      : make_uint4(0, 0, 0, 0);

        float s0 = dot_row(v0, pa, pb);
        float s1 = dot_row(v1, pa, pb);
        float s2 = dot_row(v2, pa, pb);
        float s3 = dot_row(v3, pa, pb);
#pragma unroll
        for (int off = 16; off > 0; off >>= 1) {
            s0 += __shfl_down_sync(0xffffffffu, s0, off);
            s1 += __shfl_down_sync(0xffffffffu, s1, off);
            s2 += __shfl_down_sync(0xffffffffu, s2, off);
            s3 += __shfl_down_sync(0xffffffffu, s3, off);
        }
        if (lane == 0) {
            s_logits[j] = s0;
            if (h1) s_logits[j + 8] = s1;
            if (h2) s_logits[j + 16] = s2;
            if (h3) s_logits[j + 24] = s3;
        }
    }
    __syncthreads();

    if (warp == 0) {
        float v0 = s_logits[lane];
        float v1 = s_logits[lane + 32];
        float v2 = (lane == 0) ? s_logits[64] : -INFINITY;
        float m = fmaxf(fmaxf(v0, v1), v2);
#pragma unroll
        for (int off = 16; off > 0; off >>= 1)
            m = fmaxf(m, __shfl_xor_sync(0xffffffffu, m, off));
        float s = expf(v0 - m) + expf(v1 - m) + ((lane == 0) ? expf(v2 - m) : 0.0f);
#pragma unroll
        for (int off = 16; off > 0; off >>= 1)
            s += __shfl_xor_sync(0xffffffffu, s, off);
        float lse = m + logf(s);
        if (lane == 0)
            atomicAdd(out, (lse - s_logits[0]) * (1.0f / (float)NG));
    }
}

// ---------------------------------------------------------------------------
extern "C" void kernel_launch(void* const* d_in, const int* in_sizes, int n_in,
                              void* d_out, int out_size) {
    const float* emb  = (const float*)d_in[0];   // (16384, 256) f32
    const float* W    = (const float*)d_in[1];   // (768, 256)   f32
    const float* bias = (const float*)d_in[2];   // (256,)       f32
    // d_in[3] = target (analytic, unused)
    const int* perm   = (const int*)d_in[4];     // (4096, 64)   int32

    convert_kernel<<<EMB_BLOCKS + WT_TILES, 256>>>(emb, W, (float*)d_out);
    dim3 ggrid(H / 64, NG / 64, ZSPLIT);   // (4, 64, 4) = 1024 blocks
    gemm_bf16<<<ggrid, 128>>>(bias);
    loss_kernel<<<NG, 256>>>(perm, (float*)d_out);
}

// round 12
// speedup vs baseline: 1.1151x; 1.1151x over previous
#include <cuda_runtime.h>
#include <cuda_bf16.h>
#include <math.h>
#include <stdint.h>

// Problem constants
#define NG    4096
#define KPOS  4
#define H     256
#define MNEG  64
#define NROWS (NG * KPOS)       // 16384 embedding rows
#define KDIM  768               // (KPOS-1)*H
#define LDAH  1024              // halves per emb row-group in g_Ebf (KPOS*H)
#define NLOG  65

#define ZSPLIT 4
#define KS    (KDIM / ZSPLIT)   // 192 k per z-block

// Scratch (static device arrays; allocation-free rule)
__device__ __align__(16) __nv_bfloat16 g_Ebf[NROWS * H];   // full emb, bf16 (8 MB)
__device__ __align__(16) __nv_bfloat16 g_WTbf[H * KDIM];   // W^T, bf16, [n][k]
__device__ float g_pred4[ZSPLIT * NG * H];                 // split-K partials

// ---------------------------------------------------------------------------
// Kernel 0: convert (R10 form). emb -> bf16, 8 floats/thread;
// W -> bf16 transposed via 32x32 smem tile. Block 0 zeroes out[0].
// ---------------------------------------------------------------------------
#define EMB_OCTS   (NROWS * H / 8)        // 524288
#define EMB_BLOCKS (EMB_OCTS / 256)       // 2048
#define WT_TILES   ((KDIM / 32) * (H / 32))   // 192

__global__ __launch_bounds__(256) void convert_kernel(const float* __restrict__ emb,
                                                      const float* __restrict__ W,
                                                      float* __restrict__ out) {
    int b = blockIdx.x;
    if (b == 0 && threadIdx.x == 0) out[0] = 0.0f;   // reset accumulator
    if (b < EMB_BLOCKS) {
        size_t idx = (size_t)(b * 256 + threadIdx.x) * 8;
        const float4* src = (const float4*)(emb + idx);
        float4 v0 = src[0];
        float4 v1 = src[1];
        uint4 o;
        *(__nv_bfloat162*)&o.x = __floats2bfloat162_rn(v0.x, v0.y);
        *(__nv_bfloat162*)&o.y = __floats2bfloat162_rn(v0.z, v0.w);
        *(__nv_bfloat162*)&o.z = __floats2bfloat162_rn(v1.x, v1.y);
        *(__nv_bfloat162*)&o.w = __floats2bfloat162_rn(v1.z, v1.w);
        *(uint4*)&g_Ebf[idx] = o;
    } else {
        // W^T tile transpose: tile covers k0..k0+31, n0..n0+31
        __shared__ float tile[32][33];
        int b2 = b - EMB_BLOCKS;
        int n0 = (b2 & 7) * 32;
        int k0 = (b2 >> 3) * 32;
        int tx = threadIdx.x & 31;
        int ty = threadIdx.x >> 5;        // 0..7
#pragma unroll
        for (int i = 0; i < 4; i++) {
            int k = ty + 8 * i;
            tile[k][tx] = W[(size_t)(k0 + k) * H + n0 + tx];  // coalesced read
        }
        __syncthreads();
#pragma unroll
        for (int i = 0; i < 4; i++) {
            int n = ty + 8 * i;
            g_WTbf[(size_t)(n0 + n) * KDIM + k0 + tx] =
                __float2bfloat16_rn(tile[tx][n]);             // coalesced write
        }
    }
}

// ---------------------------------------------------------------------------
// Kernel A: predicts = hist_x @ W + b  via bf16 mma.m16n8k16, fp32 accum.
// BM=64 BN=64 BK=16, 128 threads = 4 warps (2x2), warp tile 32x32.
// Grid (4, 64, 4): z = split-K quarter (K=192 each) into g_pred4.
// ---------------------------------------------------------------------------
#define BKH 16                       // k halves per iteration
#define ITERS (KS / BKH)             // 12
#define STG 4
#define ROWH 24                      // padded halves per smem row (conflict-free)
#define A_ST_H (64 * ROWH)           // 1536 halves
#define STAGE_H (2 * A_ST_H)         // 3072 halves = 6144 B

__device__ __forceinline__ void cp16b(__nv_bfloat16* dst_smem, const __nv_bfloat16* src) {
    uint32_t d = (uint32_t)__cvta_generic_to_shared(dst_smem);
    asm volatile("cp.async.cg.shared.global [%0], [%1], 16;\n" :: "r"(d), "l"(src));
}

__global__ __launch_bounds__(128) void gemm_bf16(const float* __restrict__ bias) {
    __shared__ __align__(16) __nv_bfloat16 smem[STG * STAGE_H];

    const int tid  = threadIdx.x;
    const int warp = tid >> 5;
    const int lane = tid & 31;
    const int gid  = lane >> 2;          // mma groupID
    const int tq   = lane & 3;           // mma threadID-in-group
    const int wm0  = (warp >> 1) * 32;
    const int wn0  = (warp & 1) * 32;
    const int bm0  = blockIdx.y * 64;
    const int bn0  = blockIdx.x * 64;
    const int kz   = blockIdx.z * KS;

    const int crow = tid >> 1;           // 0..63
    const int koff = (tid & 1) * 8;      // halves

    const __nv_bfloat16* Asrc = g_Ebf  + (size_t)(bm0 + crow) * LDAH + kz + koff;
    const __nv_bfloat16* Bsrc = g_WTbf + (size_t)(bn0 + crow) * KDIM + kz + koff;

    float c[2][4][4];
#pragma unroll
    for (int i = 0; i < 2; i++)
#pragma unroll
        for (int j = 0; j < 4; j++)
#pragma unroll
            for (int q = 0; q < 4; q++) c[i][j][q] = 0.0f;

#pragma unroll
    for (int s = 0; s < STG - 1; s++) {
        __nv_bfloat16* st = smem + s * STAGE_H;
        cp16b(st + crow * ROWH + koff, Asrc + s * BKH);
        cp16b(st + A_ST_H + crow * ROWH + koff, Bsrc + s * BKH);
        asm volatile("cp.async.commit_group;\n" ::: "memory");
    }

#pragma unroll 4
    for (int it = 0; it < ITERS; it++) {
        asm volatile("cp.async.wait_group 2;\n" ::: "memory");
        __syncthreads();

        int nit = it + STG - 1;
        if (nit < ITERS) {
            __nv_bfloat16* st = smem + (nit % STG) * STAGE_H;
            cp16b(st + crow * ROWH + koff, Asrc + nit * BKH);
            cp16b(st + A_ST_H + crow * ROWH + koff, Bsrc + nit * BKH);
        }
        asm volatile("cp.async.commit_group;\n" ::: "memory");

        const __nv_bfloat16* As = smem + (it % STG) * STAGE_H;
        const __nv_bfloat16* Bs = As + A_ST_H;

        uint32_t a[2][4], b[4][2];
#pragma unroll
        for (int mf = 0; mf < 2; mf++) {
            int m = wm0 + mf * 16 + gid;
            a[mf][0] = *(const uint32_t*)&As[m * ROWH + 2 * tq];
            a[mf][1] = *(const uint32_t*)&As[(m + 8) * ROWH + 2 * tq];
            a[mf][2] = *(const uint32_t*)&As[m * ROWH + 2 * tq + 8];
            a[mf][3] = *(const uint32_t*)&As[(m + 8) * ROWH + 2 * tq + 8];
        }
#pragma unroll
        for (int nf = 0; nf < 4; nf++) {
            int n = wn0 + nf * 8 + gid;
            b[nf][0] = *(const uint32_t*)&Bs[n * ROWH + 2 * tq];
            b[nf][1] = *(const uint32_t*)&Bs[n * ROWH + 2 * tq + 8];
        }
#pragma unroll
        for (int mf = 0; mf < 2; mf++)
#pragma unroll
            for (int nf = 0; nf < 4; nf++) {
                asm volatile(
                    "mma.sync.aligned.m16n8k16.row.col.f32.bf16.bf16.f32 "
                    "{%0,%1,%2,%3}, {%4,%5,%6,%7}, {%8,%9}, {%0,%1,%2,%3};"
                    : "+f"(c[mf][nf][0]), "+f"(c[mf][nf][1]),
                      "+f"(c[mf][nf][2]), "+f"(c[mf][nf][3])
                    : "r"(a[mf][0]), "r"(a[mf][1]), "r"(a[mf][2]), "r"(a[mf][3]),
                      "r"(b[nf][0]), "r"(b[nf][1]));
            }
    }

    float* outb = g_pred4 + (size_t)blockIdx.z * NG * H;
#pragma unroll
    for (int mf = 0; mf < 2; mf++) {
        int m = bm0 + wm0 + mf * 16 + gid;
#pragma unroll
        for (int nf = 0; nf < 4; nf++) {
            int n = bn0 + wn0 + nf * 8 + 2 * tq;
            float bx = 0.0f, by = 0.0f;
            if (blockIdx.z == 0) {
                float2 bb = *(const float2*)(bias + n);
                bx = bb.x; by = bb.y;
            }
            *(float2*)&outb[(size_t)m * H + n] =
                make_float2(c[mf][nf][0] + bx, c[mf][nf][1] + by);
            *(float2*)&outb[(size_t)(m + 8) * H + n] =
                make_float2(c[mf][nf][2] + bx, c[mf][nf][3] + by);
        }
    }
}

// ---------------------------------------------------------------------------
// Kernel B: per-group logits + log-softmax -> atomicAdd into out[0].
// Predicate-free x4 gather: warp w owns rows [8w, 8w+8) as two batches of
// 4 unconditional loads; row 64 is a single tail on warp 0.
// ---------------------------------------------------------------------------
__device__ __forceinline__ float dot_row(uint4 v, float4 pa, float4 pb) {
    float2 f0 = __bfloat1622float2(*(const __nv_bfloat162*)&v.x);
    float2 f1 = __bfloat1622float2(*(const __nv_bfloat162*)&v.y);
    float2 f2 = __bfloat1622float2(*(const __nv_bfloat162*)&v.z);
    float2 f3 = __bfloat1622float2(*(const __nv_bfloat162*)&v.w);
    return f0.x * pa.x + f0.y * pa.y + f1.x * pa.z + f1.y * pa.w
         + f2.x * pb.x + f2.y * pb.y + f3.x * pb.z + f3.y * pb.w;
}

__global__ __launch_bounds__(256) void loss_kernel(const int* __restrict__ perm,
                                                   float* __restrict__ out) {
    const int g    = blockIdx.x;
    const int tid  = threadIdx.x;
    const int warp = tid >> 5;
    const int lane = tid & 31;

    __shared__ float s_pred[H];
    __shared__ float s_logits[NLOG];
    __shared__ int   s_row[NLOG];

    {
        const float* pp = g_pred4 + (size_t)g * H + tid;
        s_pred[tid] = (pp[0] + pp[(size_t)NG * H])
                    + (pp[2 * (size_t)NG * H] + pp[3 * (size_t)NG * H]);
    }
    if (tid < MNEG) {
        int p = perm[(size_t)g * MNEG + tid];
        s_row[tid + 1] = p + ((p >= 4 * g) ? 4 : 0);
    }
    if (tid == MNEG) s_row[0] = 4 * g + 3;
    __syncthreads();

    // each lane owns 8 consecutive pred floats (halves 8*lane .. 8*lane+7)
    const float4* p4 = (const float4*)s_pred;
    const float4 pa = p4[2 * lane];
    const float4 pb = p4[2 * lane + 1];

    // warp w: rows [8w, 8w+8), two unconditional batches of 4
#pragma unroll
    for (int batch = 0; batch < 2; batch++) {
        int j = warp * 8 + batch * 4;
        uint4 v0 = ((const uint4*)(g_Ebf + (size_t)s_row[j + 0] * H))[lane];
        uint4 v1 = ((const uint4*)(g_Ebf + (size_t)s_row[j + 1] * H))[lane];
        uint4 v2 = ((const uint4*)(g_Ebf + (size_t)s_row[j + 2] * H))[lane];
        uint4 v3 = ((const uint4*)(g_Ebf + (size_t)s_row[j + 3] * H))[lane];
        float s0 = dot_row(v0, pa, pb);
        float s1 = dot_row(v1, pa, pb);
        float s2 = dot_row(v2, pa, pb);
        float s3 = dot_row(v3, pa, pb);
#pragma unroll
        for (int off = 16; off > 0; off >>= 1) {
            s0 += __shfl_down_sync(0xffffffffu, s0, off);
            s1 += __shfl_down_sync(0xffffffffu, s1, off);
            s2 += __shfl_down_sync(0xffffffffu, s2, off);
            s3 += __shfl_down_sync(0xffffffffu, s3, off);
        }
        if (lane == 0) {
            s_logits[j + 0] = s0;
            s_logits[j + 1] = s1;
            s_logits[j + 2] = s2;
            s_logits[j + 3] = s3;
        }
    }
    // tail row 64 on warp 0
    if (warp == 0) {
        uint4 v = ((const uint4*)(g_Ebf + (size_t)s_row[64] * H))[lane];
        float s = dot_row(v, pa, pb);
#pragma unroll
        for (int off = 16; off > 0; off >>= 1)
            s += __shfl_down_sync(0xffffffffu, s, off);
        if (lane == 0) s_logits[64] = s;
    }
    __syncthreads();

    if (warp == 0) {
        float v0 = s_logits[lane];
        float v1 = s_logits[lane + 32];
        float v2 = (lane == 0) ? s_logits[64] : -INFINITY;
        float m = fmaxf(fmaxf(v0, v1), v2);
#pragma unroll
        for (int off = 16; off > 0; off >>= 1)
            m = fmaxf(m, __shfl_xor_sync(0xffffffffu, m, off));
        float s = expf(v0 - m) + expf(v1 - m) + ((lane == 0) ? expf(v2 - m) : 0.0f);
#pragma unroll
        for (int off = 16; off > 0; off >>= 1)
            s += __shfl_xor_sync(0xffffffffu, s, off);
        float lse = m + logf(s);
        if (lane == 0)
            atomicAdd(out, (lse - s_logits[0]) * (1.0f / (float)NG));
    }
}

// ---------------------------------------------------------------------------
extern "C" void kernel_launch(void* const* d_in, const int* in_sizes, int n_in,
                              void* d_out, int out_size) {
    const float* emb  = (const float*)d_in[0];   // (16384, 256) f32
    const float* W    = (const float*)d_in[1];   // (768, 256)   f32
    const float* bias = (const float*)d_in[2];   // (256,)       f32
    // d_in[3] = target (analytic, unused)
    const int* perm   = (const int*)d_in[4];     // (4096, 64)   int32

    convert_kernel<<<EMB_BLOCKS + WT_TILES, 256>>>(emb, W, (float*)d_out);
    dim3 ggrid(H / 64, NG / 64, ZSPLIT);   // (4, 64, 4) = 1024 blocks
    gemm_bf16<<<ggrid, 128>>>(bias);
    loss_kernel<<<NG, 256>>>(perm, (float*)d_out);
}

// round 14
// speedup vs baseline: 1.1740x; 1.0528x over previous
#include <cuda_runtime.h>
#include <cuda_bf16.h>
#include <math.h>
#include <stdint.h>

// Problem constants
#define NG    4096
#define KPOS  4
#define H     256
#define MNEG  64
#define NROWS (NG * KPOS)       // 16384 embedding rows
#define KDIM  768               // (KPOS-1)*H
#define LDAH  1024              // halves per emb row-group in g_Ebf (KPOS*H)
#define NLOG  65

#define ZSPLIT 4
#define KS    (KDIM / ZSPLIT)   // 192 k per z-block

// Scratch (static device arrays; allocation-free rule)
__device__ __align__(16) __nv_bfloat16 g_Ebf[NROWS * H];   // full emb, bf16 (8 MB)
__device__ __align__(16) __nv_bfloat16 g_WTbf[H * KDIM];   // W^T, bf16, [n][k]
__device__ float g_pred4[ZSPLIT * NG * H];                 // split-K partials

// ---------------------------------------------------------------------------
// Kernel 0: convert (R10/R12 form). emb -> bf16, 8 floats/thread;
// W -> bf16 transposed via 32x32 smem tile. Block 0 zeroes out[0].
// ---------------------------------------------------------------------------
#define EMB_OCTS   (NROWS * H / 8)        // 524288
#define EMB_BLOCKS (EMB_OCTS / 256)       // 2048
#define WT_TILES   ((KDIM / 32) * (H / 32))   // 192

__global__ __launch_bounds__(256) void convert_kernel(const float* __restrict__ emb,
                                                      const float* __restrict__ W,
                                                      float* __restrict__ out) {
    int b = blockIdx.x;
    if (b == 0 && threadIdx.x == 0) out[0] = 0.0f;   // reset accumulator
    if (b < EMB_BLOCKS) {
        size_t idx = (size_t)(b * 256 + threadIdx.x) * 8;
        const float4* src = (const float4*)(emb + idx);
        float4 v0 = src[0];
        float4 v1 = src[1];
        uint4 o;
        *(__nv_bfloat162*)&o.x = __floats2bfloat162_rn(v0.x, v0.y);
        *(__nv_bfloat162*)&o.y = __floats2bfloat162_rn(v0.z, v0.w);
        *(__nv_bfloat162*)&o.z = __floats2bfloat162_rn(v1.x, v1.y);
        *(__nv_bfloat162*)&o.w = __floats2bfloat162_rn(v1.z, v1.w);
        *(uint4*)&g_Ebf[idx] = o;
    } else {
        // W^T tile transpose: tile covers k0..k0+31, n0..n0+31
        __shared__ float tile[32][33];
        int b2 = b - EMB_BLOCKS;
        int n0 = (b2 & 7) * 32;
        int k0 = (b2 >> 3) * 32;
        int tx = threadIdx.x & 31;
        int ty = threadIdx.x >> 5;        // 0..7
#pragma unroll
        for (int i = 0; i < 4; i++) {
            int k = ty + 8 * i;
            tile[k][tx] = W[(size_t)(k0 + k) * H + n0 + tx];  // coalesced read
        }
        __syncthreads();
#pragma unroll
        for (int i = 0; i < 4; i++) {
            int n = ty + 8 * i;
            g_WTbf[(size_t)(n0 + n) * KDIM + k0 + tx] =
                __float2bfloat16_rn(tile[tx][n]);             // coalesced write
        }
    }
}

// ---------------------------------------------------------------------------
// Kernel A: predicts = hist_x @ W + b  via bf16 mma.m16n8k16, fp32 accum.
// BM=64 BN=128 BK=32, 256 threads = 8 warps (2x4), warp tile 32x32.
// Grid (2, 64, 4): z = split-K quarter (K=192, 6 iters) into g_pred4.
// 3-stage cp.async pipeline; A traffic halved vs BN=64 (2 N-tiles not 4).
// ---------------------------------------------------------------------------
#define BKH 32                       // k halves per iteration
#define ITERS (KS / BKH)             // 6
#define STG 3
#define ROWH 40                      // 32 data + 8 pad halves (conflict-free)
#define A_ST_H (64 * ROWH)           // 2560 halves
#define B_ST_H (128 * ROWH)          // 5120 halves
#define STAGE_H (A_ST_H + B_ST_H)    // 7680 halves = 15360 B; x3 = 46080 B

__device__ __forceinline__ void cp16b(__nv_bfloat16* dst_smem, const __nv_bfloat16* src) {
    uint32_t d = (uint32_t)__cvta_generic_to_shared(dst_smem);
    asm volatile("cp.async.cg.shared.global [%0], [%1], 16;\n" :: "r"(d), "l"(src));
}

__global__ __launch_bounds__(256) void gemm_bf16(const float* __restrict__ bias) {
    __shared__ __align__(16) __nv_bfloat16 smem[STG * STAGE_H];

    const int tid  = threadIdx.x;
    const int warp = tid >> 5;
    const int lane = tid & 31;
    const int gid  = lane >> 2;          // mma groupID
    const int tq   = lane & 3;           // mma threadID-in-group
    const int wm0  = (warp >> 2) * 32;   // 2 m-tiles
    const int wn0  = (warp & 3) * 32;    // 4 n-tiles
    const int bm0  = blockIdx.y * 64;
    const int bn0  = blockIdx.x * 128;
    const int kz   = blockIdx.z * KS;

    // cp.async mapping: chunk = 16 B = 8 halves
    const int crow = tid >> 2;           // 0..63
    const int ckoff = (tid & 3) * 8;     // halves {0,8,16,24}

    const __nv_bfloat16* Asrc = g_Ebf  + (size_t)(bm0 + crow) * LDAH + kz + ckoff;
    const __nv_bfloat16* Bsrc0 = g_WTbf + (size_t)(bn0 + crow) * KDIM + kz + ckoff;
    const __nv_bfloat16* Bsrc1 = Bsrc0 + (size_t)64 * KDIM;

    float c[2][4][4];
#pragma unroll
    for (int i = 0; i < 2; i++)
#pragma unroll
        for (int j = 0; j < 4; j++)
#pragma unroll
            for (int q = 0; q < 4; q++) c[i][j][q] = 0.0f;

#pragma unroll
    for (int s = 0; s < STG - 1; s++) {
        __nv_bfloat16* st = smem + s * STAGE_H;
        cp16b(st + crow * ROWH + ckoff, Asrc + s * BKH);
        cp16b(st + A_ST_H + crow * ROWH + ckoff, Bsrc0 + s * BKH);
        cp16b(st + A_ST_H + (crow + 64) * ROWH + ckoff, Bsrc1 + s * BKH);
        asm volatile("cp.async.commit_group;\n" ::: "memory");
    }

#pragma unroll 3
    for (int it = 0; it < ITERS; it++) {
        asm volatile("cp.async.wait_group 1;\n" ::: "memory");
        __syncthreads();

        int nit = it + STG - 1;
        if (nit < ITERS) {
            __nv_bfloat16* st = smem + (nit % STG) * STAGE_H;
            cp16b(st + crow * ROWH + ckoff, Asrc + nit * BKH);
            cp16b(st + A_ST_H + crow * ROWH + ckoff, Bsrc0 + nit * BKH);
            cp16b(st + A_ST_H + (crow + 64) * ROWH + ckoff, Bsrc1 + nit * BKH);
        }
        asm volatile("cp.async.commit_group;\n" ::: "memory");

        const __nv_bfloat16* As = smem + (it % STG) * STAGE_H;
        const __nv_bfloat16* Bs = As + A_ST_H;

#pragma unroll
        for (int ks = 0; ks < 2; ks++) {     // two k16 steps per BK=32
            const int kb = ks * 16;
            uint32_t a[2][4], b[4][2];
#pragma unroll
            for (int mf = 0; mf < 2; mf++) {
                int m = wm0 + mf * 16 + gid;
                a[mf][0] = *(const uint32_t*)&As[m * ROWH + kb + 2 * tq];
                a[mf][1] = *(const uint32_t*)&As[(m + 8) * ROWH + kb + 2 * tq];
                a[mf][2] = *(const uint32_t*)&As[m * ROWH + kb + 2 * tq + 8];
                a[mf][3] = *(const uint32_t*)&As[(m + 8) * ROWH + kb + 2 * tq + 8];
            }
#pragma unroll
            for (int nf = 0; nf < 4; nf++) {
                int n = wn0 + nf * 8 + gid;
                b[nf][0] = *(const uint32_t*)&Bs[n * ROWH + kb + 2 * tq];
                b[nf][1] = *(const uint32_t*)&Bs[n * ROWH + kb + 2 * tq + 8];
            }
#pragma unroll
            for (int mf = 0; mf < 2; mf++)
#pragma unroll
                for (int nf = 0; nf < 4; nf++) {
                    asm volatile(
                        "mma.sync.aligned.m16n8k16.row.col.f32.bf16.bf16.f32 "
                        "{%0,%1,%2,%3}, {%4,%5,%6,%7}, {%8,%9}, {%0,%1,%2,%3};"
                        : "+f"(c[mf][nf][0]), "+f"(c[mf][nf][1]),
                          "+f"(c[mf][nf][2]), "+f"(c[mf][nf][3])
                        : "r"(a[mf][0]), "r"(a[mf][1]), "r"(a[mf][2]), "r"(a[mf][3]),
                          "r"(b[nf][0]), "r"(b[nf][1]));
                }
        }
    }

    float* outb = g_pred4 + (size_t)blockIdx.z * NG * H;
#pragma unroll
    for (int mf = 0; mf < 2; mf++) {
        int m = bm0 + wm0 + mf * 16 + gid;
#pragma unroll
        for (int nf = 0; nf < 4; nf++) {
            int n = bn0 + wn0 + nf * 8 + 2 * tq;
            float bx = 0.0f, by = 0.0f;
            if (blockIdx.z == 0) {
                float2 bb = *(const float2*)(bias + n);
                bx = bb.x; by = bb.y;
            }
            *(float2*)&outb[(size_t)m * H + n] =
                make_float2(c[mf][nf][0] + bx, c[mf][nf][1] + by);
            *(float2*)&outb[(size_t)(m + 8) * H + n] =
                make_float2(c[mf][nf][2] + bx, c[mf][nf][3] + by);
        }
    }
}

// ---------------------------------------------------------------------------
// Kernel B: per-group logits + log-softmax -> atomicAdd into out[0].
// Predicate-free x4 gather (R12 form).
// ---------------------------------------------------------------------------
__device__ __forceinline__ float dot_row(uint4 v, float4 pa, float4 pb) {
    float2 f0 = __bfloat1622float2(*(const __nv_bfloat162*)&v.x);
    float2 f1 = __bfloat1622float2(*(const __nv_bfloat162*)&v.y);
    float2 f2 = __bfloat1622float2(*(const __nv_bfloat162*)&v.z);
    float2 f3 = __bfloat1622float2(*(const __nv_bfloat162*)&v.w);
    return f0.x * pa.x + f0.y * pa.y + f1.x * pa.z + f1.y * pa.w
         + f2.x * pb.x + f2.y * pb.y + f3.x * pb.z + f3.y * pb.w;
}

__global__ __launch_bounds__(256) void loss_kernel(const int* __restrict__ perm,
                                                   float* __restrict__ out) {
    const int g    = blockIdx.x;
    const int tid  = threadIdx.x;
    const int warp = tid >> 5;
    const int lane = tid & 31;

    __shared__ float s_pred[H];
    __shared__ float s_logits[NLOG];
    __shared__ int   s_row[NLOG];

    {
        const float* pp = g_pred4 + (size_t)g * H + tid;
        s_pred[tid] = (pp[0] + pp[(size_t)NG * H])
                    + (pp[2 * (size_t)NG * H] + pp[3 * (size_t)NG * H]);
    }
    if (tid < MNEG) {
        int p = perm[(size_t)g * MNEG + tid];
        s_row[tid + 1] = p + ((p >= 4 * g) ? 4 : 0);
    }
    if (tid == MNEG) s_row[0] = 4 * g + 3;
    __syncthreads();

    // each lane owns 8 consecutive pred floats (halves 8*lane .. 8*lane+7)
    const float4* p4 = (const float4*)s_pred;
    const float4 pa = p4[2 * lane];
    const float4 pb = p4[2 * lane + 1];

    // warp w: rows [8w, 8w+8), two unconditional batches of 4
#pragma unroll
    for (int batch = 0; batch < 2; batch++) {
        int j = warp * 8 + batch * 4;
        uint4 v0 = ((const uint4*)(g_Ebf + (size_t)s_row[j + 0] * H))[lane];
        uint4 v1 = ((const uint4*)(g_Ebf + (size_t)s_row[j + 1] * H))[lane];
        uint4 v2 = ((const uint4*)(g_Ebf + (size_t)s_row[j + 2] * H))[lane];
        uint4 v3 = ((const uint4*)(g_Ebf + (size_t)s_row[j + 3] * H))[lane];
        float s0 = dot_row(v0, pa, pb);
        float s1 = dot_row(v1, pa, pb);
        float s2 = dot_row(v2, pa, pb);
        float s3 = dot_row(v3, pa, pb);
#pragma unroll
        for (int off = 16; off > 0; off >>= 1) {
            s0 += __shfl_down_sync(0xffffffffu, s0, off);
            s1 += __shfl_down_sync(0xffffffffu, s1, off);
            s2 += __shfl_down_sync(0xffffffffu, s2, off);
            s3 += __shfl_down_sync(0xffffffffu, s3, off);
        }
        if (lane == 0) {
            s_logits[j + 0] = s0;
            s_logits[j + 1] = s1;
            s_logits[j + 2] = s2;
            s_logits[j + 3] = s3;
        }
    }
    // tail row 64 on warp 0
    if (warp == 0) {
        uint4 v = ((const uint4*)(g_Ebf + (size_t)s_row[64] * H))[lane];
        float s = dot_row(v, pa, pb);
#pragma unroll
        for (int off = 16; off > 0; off >>= 1)
            s += __shfl_down_sync(0xffffffffu, s, off);
        if (lane == 0) s_logits[64] = s;
    }
    __syncthreads();

    if (warp == 0) {
        float v0 = s_logits[lane];
        float v1 = s_logits[lane + 32];
        float v2 = (lane == 0) ? s_logits[64] : -INFINITY;
        float m = fmaxf(fmaxf(v0, v1), v2);
#pragma unroll
        for (int off = 16; off > 0; off >>= 1)
            m = fmaxf(m, __shfl_xor_sync(0xffffffffu, m, off));
        float s = expf(v0 - m) + expf(v1 - m) + ((lane == 0) ? expf(v2 - m) : 0.0f);
#pragma unroll
        for (int off = 16; off > 0; off >>= 1)
            s += __shfl_xor_sync(0xffffffffu, s, off);
        float lse = m + logf(s);
        if (lane == 0)
            atomicAdd(out, (lse - s_logits[0]) * (1.0f / (float)NG));
    }
}

// ---------------------------------------------------------------------------
extern "C" void kernel_launch(void* const* d_in, const int* in_sizes, int n_in,
                              void* d_out, int out_size) {
    const float* emb  = (const float*)d_in[0];   // (16384, 256) f32
    const float* W    = (const float*)d_in[1];   // (768, 256)   f32
    const float* bias = (const float*)d_in[2];   // (256,)       f32
    // d_in[3] = target (analytic, unused)
    const int* perm   = (const int*)d_in[4];     // (4096, 64)   int32

    convert_kernel<<<EMB_BLOCKS + WT_TILES, 256>>>(emb, W, (float*)d_out);
    dim3 ggrid(H / 128, NG / 64, ZSPLIT);   // (2, 64, 4) = 512 blocks
    gemm_bf16<<<ggrid, 256>>>(bias);
    loss_kernel<<<NG, 256>>>(perm, (float*)d_out);
}